// round 2
// baseline (speedup 1.0000x reference)
#include <cuda_runtime.h>

#define B_    8
#define HW_   128
#define C_    128
#define NPIX  (B_ * HW_ * HW_)   // 131072

// Scratch: v = x@Wv+bv, and the aggregation output. 64 MiB each.
__device__ float g_v[(size_t)NPIX * C_];
__device__ float g_agg[(size_t)NPIX * C_];

// -----------------------------------------------------------------------------
// GEMM: out[M,128] = A[M,128] @ W[128,128] + bias[128]
// W cached in dynamic smem (64 KB). One warp per 2 rows (ILP x2); each lane
// holds 4 A values per row (float4 load), broadcast via shfl; W rows read as
// float4 from smem (conflict-free: 8 lanes/phase x 16B = 128B contiguous).
// -----------------------------------------------------------------------------
__global__ void __launch_bounds__(256) gemm128(const float* __restrict__ A,
                                               const float* __restrict__ Wm,
                                               const float* __restrict__ bias,
                                               float* __restrict__ out,
                                               int M)
{
    extern __shared__ float Ws[];  // 128*128 floats = 64 KB
    for (int i = threadIdx.x; i < (C_ * C_) / 4; i += 256) {
        ((float4*)Ws)[i] = ((const float4*)Wm)[i];
    }
    __syncthreads();

    const int lane = threadIdx.x & 31;
    const int warp = threadIdx.x >> 5;

    const float4 b4 = ((const float4*)bias)[lane];

    // 2 rows per warp per iteration
    for (int row = (blockIdx.x * 8 + warp) * 2; row < M; row += gridDim.x * 16) {
        const float4 a4_0 = ((const float4*)(A + (size_t)row * C_))[lane];
        const float4 a4_1 = ((const float4*)(A + (size_t)(row + 1) * C_))[lane];
        const float a0[4] = {a4_0.x, a4_0.y, a4_0.z, a4_0.w};
        const float a1[4] = {a4_1.x, a4_1.y, a4_1.z, a4_1.w};
        float4 acc0 = make_float4(0.f, 0.f, 0.f, 0.f);
        float4 acc1 = make_float4(0.f, 0.f, 0.f, 0.f);

        #pragma unroll
        for (int k = 0; k < 128; k++) {
            // element k of an A row lives in lane (k>>2), slot (k&3)
            const float av0 = __shfl_sync(0xffffffffu, a0[k & 3], k >> 2);
            const float av1 = __shfl_sync(0xffffffffu, a1[k & 3], k >> 2);
            const float4 w = ((const float4*)(Ws + k * C_))[lane];
            acc0.x += av0 * w.x;  acc1.x += av1 * w.x;
            acc0.y += av0 * w.y;  acc1.y += av1 * w.y;
            acc0.z += av0 * w.z;  acc1.z += av1 * w.z;
            acc0.w += av0 * w.w;  acc1.w += av1 * w.w;
        }
        acc0.x += b4.x; acc0.y += b4.y; acc0.z += b4.z; acc0.w += b4.w;
        acc1.x += b4.x; acc1.y += b4.y; acc1.z += b4.z; acc1.w += b4.w;
        ((float4*)(out + (size_t)row * C_))[lane] = acc0;
        ((float4*)(out + (size_t)(row + 1) * C_))[lane] = acc1;
    }
}

// -----------------------------------------------------------------------------
// Superpixel-gated 7x7 neighborhood aggregation (NATTEN-style clamped window).
// One CTA per pixel, one thread per channel (warp w == head w).
// Gate is uniform across the CTA -> uniform branch, skips v load + attn load
// when the neighbor's superpixel label differs.
// -----------------------------------------------------------------------------
__global__ void __launch_bounds__(128) agg_kernel(const float* __restrict__ v,
                                                  const float* __restrict__ attn,
                                                  const int*   __restrict__ sp,
                                                  float* __restrict__ out)
{
    const int pix = blockIdx.x;           // b*H*W + y*W + x
    const int c   = threadIdx.x;
    const int x   = pix & 127;
    const int y   = (pix >> 7) & 127;
    const int b   = pix >> 14;

    const int spc = sp[pix];
    int si = y - 3; if (si < 0) si = 0; if (si > HW_ - 7) si = HW_ - 7;
    int sj = x - 3; if (sj < 0) sj = 0; if (sj > HW_ - 7) sj = HW_ - 7;

    const int h = c >> 5;
    const float* ap  = attn + ((((size_t)b * 4 + h) * HW_ + y) * HW_ + x) * 49;
    const int*   spb = sp + (size_t)b * HW_ * HW_;
    const float* vb  = v + (size_t)b * HW_ * HW_ * C_;

    float acc = 0.f;
    #pragma unroll
    for (int ki = 0; ki < 7; ki++) {
        const int ni = si + ki;
        #pragma unroll
        for (int kj = 0; kj < 7; kj++) {
            const int nj = sj + kj;
            const int np = ni * HW_ + nj;
            if (spb[np] == spc) {
                acc += ap[ki * 7 + kj] * vb[(size_t)np * C_ + c];
            }
        }
    }
    out[(size_t)pix * C_ + c] = acc;
}

// -----------------------------------------------------------------------------
// Launch: GEMM1 (x@Wv+bv) -> gated aggregation -> GEMM2 (@Wp+bp)
// -----------------------------------------------------------------------------
extern "C" void kernel_launch(void* const* d_in, const int* in_sizes, int n_in,
                              void* d_out, int out_size)
{
    const float* x    = (const float*)d_in[0];
    const float* attn = (const float*)d_in[1];
    const int*   sp   = (const int*)  d_in[2];
    const float* Wv   = (const float*)d_in[3];
    const float* bv   = (const float*)d_in[4];
    const float* Wp   = (const float*)d_in[5];
    const float* bp   = (const float*)d_in[6];
    float*       out  = (float*)d_out;

    float* vbuf = nullptr;
    float* aggbuf = nullptr;
    cudaGetSymbolAddress((void**)&vbuf, g_v);
    cudaGetSymbolAddress((void**)&aggbuf, g_agg);

    cudaFuncSetAttribute(gemm128, cudaFuncAttributeMaxDynamicSharedMemorySize, 65536);

    const int M = NPIX;
    // 148 SMs x 3 resident blocks (64KB smem each) = 444
    gemm128<<<444, 256, 65536>>>(x, Wv, bv, vbuf, M);
    agg_kernel<<<NPIX, 128>>>(vbuf, attn, sp, aggbuf);
    gemm128<<<444, 256, 65536>>>(aggbuf, Wp, bp, out, M);
}

// round 3
// speedup vs baseline: 3.4403x; 3.4403x over previous
#include <cuda_runtime.h>

#define B_    8
#define HW_   128
#define C_    128
#define NPIX  (B_ * HW_ * HW_)   // 131072

// Scratch: v = x@Wv+bv, and the aggregation output. 64 MiB each.
__device__ float g_v[(size_t)NPIX * C_];
__device__ float g_agg[(size_t)NPIX * C_];

// ---------------------------------------------------------------------------
// packed f32x2 helpers (Blackwell sm_100+: full-rate packed fp32 FMA)
// ---------------------------------------------------------------------------
__device__ __forceinline__ unsigned long long pack2(float lo, float hi) {
    unsigned long long r;
    asm("mov.b64 %0, {%1, %2};" : "=l"(r) : "f"(lo), "f"(hi));
    return r;
}
__device__ __forceinline__ unsigned long long fma2(unsigned long long a,
                                                   unsigned long long b,
                                                   unsigned long long c) {
    unsigned long long d;
    asm("fma.rn.f32x2 %0, %1, %2, %3;" : "=l"(d) : "l"(a), "l"(b), "l"(c));
    return d;
}
__device__ __forceinline__ unsigned long long add2(unsigned long long a,
                                                   unsigned long long b) {
    unsigned long long d;
    asm("add.rn.f32x2 %0, %1, %2;" : "=l"(d) : "l"(a), "l"(b));
    return d;
}

// ---------------------------------------------------------------------------
// SGEMM: out[M,128] = A[M,128] @ W[128,128] + bias[128]
// BM=128 rows per CTA, BN=128 (full), BK=16. 256 threads, 8x8 micro-tile,
// packed f32x2 accumulators (4 col-pairs at cols {0,32,64,96}+tx*2).
// ---------------------------------------------------------------------------
#define BK 16
__global__ void __launch_bounds__(256, 2) gemm128(const float* __restrict__ A,
                                                  const float* __restrict__ Wm,
                                                  const float* __restrict__ bias,
                                                  float* __restrict__ out)
{
    __shared__ float As[BK][128];   // transposed A chunk: As[k][row]
    __shared__ float Ws[BK][128];   // W chunk: Ws[k][col]

    const int tid = threadIdx.x;
    const int tx  = tid & 15;       // 0..15 -> col groups
    const int ty  = tid >> 4;       // 0..15 -> row group (8 rows)
    const size_t blockRow = (size_t)blockIdx.x * 128;
    const float* Ab = A + blockRow * C_;

    unsigned long long acc[8][4];
    #pragma unroll
    for (int i = 0; i < 8; i++)
        #pragma unroll
        for (int g = 0; g < 4; g++) acc[i][g] = 0ull;

    for (int k0 = 0; k0 < C_; k0 += BK) {
        // Load A chunk (128 rows x 16 k), store transposed.
        #pragma unroll
        for (int i = 0; i < 2; i++) {
            int idx = tid + i * 256;        // 0..511 float4 slots
            int row = idx >> 2;             // 0..127
            int c4  = idx & 3;              // 0..3
            float4 a = *(const float4*)(Ab + (size_t)row * C_ + k0 + c4 * 4);
            As[c4 * 4 + 0][row] = a.x;
            As[c4 * 4 + 1][row] = a.y;
            As[c4 * 4 + 2][row] = a.z;
            As[c4 * 4 + 3][row] = a.w;
        }
        // Load W chunk (16 k x 128 cols), direct.
        #pragma unroll
        for (int i = 0; i < 2; i++) {
            int idx = tid + i * 256;        // 0..511
            int kr  = idx >> 5;             // 0..15
            int c4  = idx & 31;             // 0..31
            *(float4*)&Ws[kr][c4 * 4] =
                *(const float4*)(Wm + (size_t)(k0 + kr) * C_ + c4 * 4);
        }
        __syncthreads();

        #pragma unroll
        for (int k = 0; k < BK; k++) {
            // A: 8 row values (broadcast across warp: only 2 distinct ty/warp)
            float4 a0 = *(const float4*)&As[k][ty * 8];
            float4 a1 = *(const float4*)&As[k][ty * 8 + 4];
            float av[8] = {a0.x, a0.y, a0.z, a0.w, a1.x, a1.y, a1.z, a1.w};
            // W: 4 col-pairs at cols g*32 + tx*2 (LDS.64, conflict-free)
            unsigned long long w[4];
            #pragma unroll
            for (int g = 0; g < 4; g++) {
                float2 wf = *(const float2*)&Ws[k][g * 32 + tx * 2];
                w[g] = pack2(wf.x, wf.y);
            }
            #pragma unroll
            for (int i = 0; i < 8; i++) {
                unsigned long long ad = pack2(av[i], av[i]);
                #pragma unroll
                for (int g = 0; g < 4; g++)
                    acc[i][g] = fma2(ad, w[g], acc[i][g]);
            }
        }
        __syncthreads();
    }

    // Epilogue: add bias, store.
    unsigned long long bp[4];
    #pragma unroll
    for (int g = 0; g < 4; g++) {
        float2 bf = *(const float2*)(bias + g * 32 + tx * 2);
        bp[g] = pack2(bf.x, bf.y);
    }
    #pragma unroll
    for (int i = 0; i < 8; i++) {
        float* orow = out + (blockRow + ty * 8 + i) * C_;
        #pragma unroll
        for (int g = 0; g < 4; g++) {
            unsigned long long r = add2(acc[i][g], bp[g]);
            *(unsigned long long*)(orow + g * 32 + tx * 2) = r;
        }
    }
}

// ---------------------------------------------------------------------------
// Superpixel-gated 7x7 neighborhood aggregation. Warp per pixel.
// Gate is sparse (~1.75/49 active for random labels): lane-parallel label
// scan -> ballot mask -> iterate only active neighbors.
// Lane covers channels [lane*4, lane*4+4) => head = lane>>3.
// ---------------------------------------------------------------------------
__global__ void __launch_bounds__(256) agg_kernel(const float* __restrict__ v,
                                                  const float* __restrict__ attn,
                                                  const int*   __restrict__ sp,
                                                  float* __restrict__ out)
{
    const int lane = threadIdx.x & 31;
    const int wid  = threadIdx.x >> 5;
    const int pix  = blockIdx.x * 8 + wid;
    const int x = pix & 127;
    const int y = (pix >> 7) & 127;
    const int b = pix >> 14;

    const int*   spb = sp + (b << 14);
    const float* vb  = v + (((size_t)b << 14) * C_);
    const int spc = spb[(y << 7) | x];

    int si = y - 3; si = si < 0 ? 0 : (si > HW_ - 7 ? HW_ - 7 : si);
    int sj = x - 3; sj = sj < 0 ? 0 : (sj > HW_ - 7 ? HW_ - 7 : sj);
    const int base_np = si * HW_ + sj;

    // neighbor index k -> ki=k/7, kj=k%7 (k<49: (k*37)>>8 == k/7)
    // gate scan: k = lane (0..31) and k = lane+32 (32..48)
    int k1 = lane;
    int ki1 = (k1 * 37) >> 8;
    unsigned m0 = __ballot_sync(0xffffffffu,
                                spb[base_np + ki1 * HW_ + (k1 - ki1 * 7)] == spc);
    int k2 = lane + 32; int k2c = k2 > 48 ? 48 : k2;
    int ki2 = (k2c * 37) >> 8;
    unsigned m1 = __ballot_sync(0xffffffffu,
        (k2 < 49) && (spb[base_np + ki2 * HW_ + (k2c - ki2 * 7)] == spc));

    const float* ab = attn +
        ((((size_t)(b * 4 + (lane >> 3)) * HW_ + y) * HW_ + x)) * 49;

    float4 acc = make_float4(0.f, 0.f, 0.f, 0.f);
    while (m0) {
        int k = __ffs(m0) - 1; m0 &= m0 - 1;
        int ki = (k * 37) >> 8;
        int np = base_np + ki * HW_ + (k - ki * 7);
        float a = __ldg(ab + k);
        float4 vv = *(const float4*)(vb + (size_t)np * C_ + lane * 4);
        acc.x += a * vv.x; acc.y += a * vv.y;
        acc.z += a * vv.z; acc.w += a * vv.w;
    }
    while (m1) {
        int k = (__ffs(m1) - 1) + 32; m1 &= m1 - 1;
        int ki = (k * 37) >> 8;
        int np = base_np + ki * HW_ + (k - ki * 7);
        float a = __ldg(ab + k);
        float4 vv = *(const float4*)(vb + (size_t)np * C_ + lane * 4);
        acc.x += a * vv.x; acc.y += a * vv.y;
        acc.z += a * vv.z; acc.w += a * vv.w;
    }
    *(float4*)(out + (size_t)pix * C_ + lane * 4) = acc;
}

// ---------------------------------------------------------------------------
// Launch: GEMM1 (x@Wv+bv) -> gated aggregation -> GEMM2 (@Wp+bp)
// ---------------------------------------------------------------------------
extern "C" void kernel_launch(void* const* d_in, const int* in_sizes, int n_in,
                              void* d_out, int out_size)
{
    const float* x    = (const float*)d_in[0];
    const float* attn = (const float*)d_in[1];
    const int*   sp   = (const int*)  d_in[2];
    const float* Wv   = (const float*)d_in[3];
    const float* bv   = (const float*)d_in[4];
    const float* Wp   = (const float*)d_in[5];
    const float* bp   = (const float*)d_in[6];
    float*       out  = (float*)d_out;

    float* vbuf = nullptr;
    float* aggbuf = nullptr;
    cudaGetSymbolAddress((void**)&vbuf, g_v);
    cudaGetSymbolAddress((void**)&aggbuf, g_agg);

    gemm128<<<NPIX / 128, 256>>>(x, Wv, bv, vbuf);
    agg_kernel<<<NPIX / 8, 256>>>(vbuf, attn, sp, aggbuf);
    gemm128<<<NPIX / 128, 256>>>(aggbuf, Wp, bp, out);
}

// round 5
// speedup vs baseline: 4.4083x; 1.2813x over previous
#include <cuda_runtime.h>
#include <cuda_bf16.h>
#include <cstdint>

#define B_    8
#define HW_   128
#define C_    128
#define NPIX  (B_ * HW_ * HW_)   // 131072

// Scratch
__device__ float g_v[(size_t)NPIX * C_];
__device__ float g_agg[(size_t)NPIX * C_];
// bf16-split weights, [which][k][n] (row-major, B-operand layout)
__device__ __nv_bfloat16 g_wh[2 * C_ * C_];
__device__ __nv_bfloat16 g_wl[2 * C_ * C_];

__device__ __forceinline__ uint32_t smem_u32(const void* p) {
    uint32_t a;
    asm("{ .reg .u64 t; cvta.to.shared.u64 t, %1; cvt.u32.u64 %0, t; }"
        : "=r"(a) : "l"(p));
    return a;
}

// ---------------------------------------------------------------------------
// Weight prep: Wh[k][n], Wl[k][n] = bf16 split of W[k][n]
// ---------------------------------------------------------------------------
__global__ void prep_w(const float* __restrict__ Wv, const float* __restrict__ Wp)
{
    const float* W = blockIdx.x ? Wp : Wv;
    __nv_bfloat16* oh = g_wh + blockIdx.x * C_ * C_;
    __nv_bfloat16* ol = g_wl + blockIdx.x * C_ * C_;
    for (int i = threadIdx.x; i < C_ * C_; i += blockDim.x) {
        float x = W[i];
        __nv_bfloat16 h = __float2bfloat16_rn(x);
        oh[i] = h;
        ol[i] = __float2bfloat16_rn(x - __bfloat162float(h));
    }
}

// ---------------------------------------------------------------------------
// Tensor-core GEMM via mma.sync (sm_80+ path, works on base sm_100 target):
// out[tile 128,128] = A[128,128] @ W[128,128] + bias, split-bf16 x3 products.
// smem: Ah/Al [128][136] bf16, Bh/Bl [128][136] bf16 (stride 136 = pad 8).
// 8 warps: (wid&3) -> 32-row block, (wid>>2) -> 64-col block.
// ---------------------------------------------------------------------------
#define STRIDE 136
#define SM_AH 0
#define SM_AL (SM_AH + 128 * STRIDE * 2)     // 34816
#define SM_BH (SM_AL + 128 * STRIDE * 2)     // 69632
#define SM_BL (SM_BH + 128 * STRIDE * 2)     // 104448
#define SM_TOTAL (SM_BL + 128 * STRIDE * 2)  // 139264

__device__ __forceinline__ void ldsm_x4(uint32_t* r, uint32_t addr) {
    asm volatile("ldmatrix.sync.aligned.m8n8.x4.shared.b16 {%0,%1,%2,%3}, [%4];"
                 : "=r"(r[0]), "=r"(r[1]), "=r"(r[2]), "=r"(r[3]) : "r"(addr));
}
__device__ __forceinline__ void ldsm_x4_t(uint32_t* r, uint32_t addr) {
    asm volatile("ldmatrix.sync.aligned.m8n8.x4.trans.shared.b16 {%0,%1,%2,%3}, [%4];"
                 : "=r"(r[0]), "=r"(r[1]), "=r"(r[2]), "=r"(r[3]) : "r"(addr));
}
__device__ __forceinline__ void mma16816(float* c, const uint32_t* a,
                                         const uint32_t* b) {
    asm volatile(
        "mma.sync.aligned.m16n8k16.row.col.f32.bf16.bf16.f32 "
        "{%0,%1,%2,%3}, {%4,%5,%6,%7}, {%8,%9}, {%0,%1,%2,%3};"
        : "+f"(c[0]), "+f"(c[1]), "+f"(c[2]), "+f"(c[3])
        : "r"(a[0]), "r"(a[1]), "r"(a[2]), "r"(a[3]), "r"(b[0]), "r"(b[1]));
}

__global__ void __launch_bounds__(256, 1)
tc_gemm(const float* __restrict__ A,
        const __nv_bfloat16* __restrict__ Wh,
        const __nv_bfloat16* __restrict__ Wl,
        const float* __restrict__ bias,
        float* __restrict__ out)
{
    extern __shared__ char smem[];
    const uint32_t sb = smem_u32(smem);
    const int tid  = threadIdx.x;
    const int lane = tid & 31;
    const int wid  = tid >> 5;
    const int wm   = wid & 3;   // 32-row block
    const int wn   = wid >> 2;  // 64-col block

    // ---- Fill A (hi/lo split, padded stride) ----
    const float4* Ab = (const float4*)(A + (size_t)blockIdx.x * 128 * C_);
    #pragma unroll
    for (int it = 0; it < 16; it++) {
        const int i = tid + it * 256;       // 0..4095
        const int row = i >> 5, c4 = i & 31;
        float4 a = Ab[i];
        __nv_bfloat16 h0 = __float2bfloat16_rn(a.x);
        __nv_bfloat16 h1 = __float2bfloat16_rn(a.y);
        __nv_bfloat16 h2 = __float2bfloat16_rn(a.z);
        __nv_bfloat16 h3 = __float2bfloat16_rn(a.w);
        __nv_bfloat16 l0 = __float2bfloat16_rn(a.x - __bfloat162float(h0));
        __nv_bfloat16 l1 = __float2bfloat16_rn(a.y - __bfloat162float(h1));
        __nv_bfloat16 l2 = __float2bfloat16_rn(a.z - __bfloat162float(h2));
        __nv_bfloat16 l3 = __float2bfloat16_rn(a.w - __bfloat162float(h3));
        uint64_t hv = (uint64_t)__bfloat16_as_ushort(h0)
                    | ((uint64_t)__bfloat16_as_ushort(h1) << 16)
                    | ((uint64_t)__bfloat16_as_ushort(h2) << 32)
                    | ((uint64_t)__bfloat16_as_ushort(h3) << 48);
        uint64_t lv = (uint64_t)__bfloat16_as_ushort(l0)
                    | ((uint64_t)__bfloat16_as_ushort(l1) << 16)
                    | ((uint64_t)__bfloat16_as_ushort(l2) << 32)
                    | ((uint64_t)__bfloat16_as_ushort(l3) << 48);
        const uint32_t off = row * (STRIDE * 2) + c4 * 8;   // bytes
        *(uint64_t*)(smem + SM_AH + off) = hv;
        *(uint64_t*)(smem + SM_AL + off) = lv;
    }
    // ---- Fill B (pre-split, [k][n]) ----
    const uint4* bh4 = (const uint4*)Wh;
    const uint4* bl4 = (const uint4*)Wl;
    #pragma unroll
    for (int it = 0; it < 8; it++) {
        const int i = tid + it * 256;       // 0..2047
        const int row = i >> 4, c8 = i & 15;
        const uint32_t off = row * (STRIDE * 2) + c8 * 16;  // bytes
        *(uint4*)(smem + SM_BH + off) = bh4[i];
        *(uint4*)(smem + SM_BL + off) = bl4[i];
    }
    __syncthreads();

    // ---- Mainloop: 3 products x 8 k-steps ----
    float acc[2][8][4];
    #pragma unroll
    for (int t = 0; t < 2; t++)
        #pragma unroll
        for (int j = 0; j < 8; j++)
            #pragma unroll
            for (int e = 0; e < 4; e++) acc[t][j][e] = 0.f;

    const uint32_t a_bases[3] = {sb + SM_AH, sb + SM_AH, sb + SM_AL};
    const uint32_t b_bases[3] = {sb + SM_BH, sb + SM_BL, sb + SM_BH};
    const int arow = wm * 32 + (lane & 15);
    const int acol_off = (lane >> 4) * 8;
    const int brow = (lane & 15);
    const int bcol = wn * 64 + (lane >> 4) * 8;

    #pragma unroll
    for (int p = 0; p < 3; p++) {
        const uint32_t abase = a_bases[p];
        const uint32_t bbase = b_bases[p];
        #pragma unroll
        for (int k0 = 0; k0 < 128; k0 += 16) {
            uint32_t af[2][4];
            ldsm_x4(af[0], abase + (arow * STRIDE + k0 + acol_off) * 2);
            ldsm_x4(af[1], abase + ((arow + 16) * STRIDE + k0 + acol_off) * 2);
            #pragma unroll
            for (int g = 0; g < 4; g++) {
                uint32_t bf[4];
                ldsm_x4_t(bf, bbase + ((k0 + brow) * STRIDE + bcol + g * 16) * 2);
                mma16816(acc[0][g * 2 + 0], af[0], bf + 0);
                mma16816(acc[0][g * 2 + 1], af[0], bf + 2);
                mma16816(acc[1][g * 2 + 0], af[1], bf + 0);
                mma16816(acc[1][g * 2 + 1], af[1], bf + 2);
            }
        }
    }

    // ---- Epilogue: C frag (m16n8): c0,c1 row lane/4 cols (lane%4)*2; c2,c3 row+8
    const int r0 = wm * 32 + (lane >> 2);
    const int cb = wn * 64 + (lane & 3) * 2;
    float* ob = out + (size_t)blockIdx.x * 128 * C_;
    #pragma unroll
    for (int j = 0; j < 8; j++) {
        const int col = cb + j * 8;
        const float2 bias2 = *(const float2*)(bias + col);
        #pragma unroll
        for (int t = 0; t < 2; t++) {
            float* rowp0 = ob + (size_t)(r0 + t * 16) * C_ + col;
            float* rowp1 = ob + (size_t)(r0 + t * 16 + 8) * C_ + col;
            float2 v0 = make_float2(acc[t][j][0] + bias2.x, acc[t][j][1] + bias2.y);
            float2 v1 = make_float2(acc[t][j][2] + bias2.x, acc[t][j][3] + bias2.y);
            *(float2*)rowp0 = v0;
            *(float2*)rowp1 = v1;
        }
    }
}

// ---------------------------------------------------------------------------
// Superpixel-gated 7x7 neighborhood aggregation. Warp per pixel (~38us).
// ---------------------------------------------------------------------------
__global__ void __launch_bounds__(256) agg_kernel(const float* __restrict__ v,
                                                  const float* __restrict__ attn,
                                                  const int*   __restrict__ sp,
                                                  float* __restrict__ out)
{
    const int lane = threadIdx.x & 31;
    const int wid  = threadIdx.x >> 5;
    const int pix  = blockIdx.x * 8 + wid;
    const int x = pix & 127;
    const int y = (pix >> 7) & 127;
    const int b = pix >> 14;

    const int*   spb = sp + (b << 14);
    const float* vb  = v + (((size_t)b << 14) * C_);
    const int spc = spb[(y << 7) | x];

    int si = y - 3; si = si < 0 ? 0 : (si > HW_ - 7 ? HW_ - 7 : si);
    int sj = x - 3; sj = sj < 0 ? 0 : (sj > HW_ - 7 ? HW_ - 7 : sj);
    const int base_np = si * HW_ + sj;

    int k1 = lane;
    int ki1 = (k1 * 37) >> 8;
    unsigned m0 = __ballot_sync(0xffffffffu,
                                spb[base_np + ki1 * HW_ + (k1 - ki1 * 7)] == spc);
    int k2 = lane + 32; int k2c = k2 > 48 ? 48 : k2;
    int ki2 = (k2c * 37) >> 8;
    unsigned m1 = __ballot_sync(0xffffffffu,
        (k2 < 49) && (spb[base_np + ki2 * HW_ + (k2c - ki2 * 7)] == spc));

    const float* ab = attn +
        ((((size_t)(b * 4 + (lane >> 3)) * HW_ + y) * HW_ + x)) * 49;

    float4 acc = make_float4(0.f, 0.f, 0.f, 0.f);
    while (m0) {
        int k = __ffs(m0) - 1; m0 &= m0 - 1;
        int ki = (k * 37) >> 8;
        int np = base_np + ki * HW_ + (k - ki * 7);
        float a = __ldg(ab + k);
        float4 vv = *(const float4*)(vb + (size_t)np * C_ + lane * 4);
        acc.x += a * vv.x; acc.y += a * vv.y;
        acc.z += a * vv.z; acc.w += a * vv.w;
    }
    while (m1) {
        int k = (__ffs(m1) - 1) + 32; m1 &= m1 - 1;
        int ki = (k * 37) >> 8;
        int np = base_np + ki * HW_ + (k - ki * 7);
        float a = __ldg(ab + k);
        float4 vv = *(const float4*)(vb + (size_t)np * C_ + lane * 4);
        acc.x += a * vv.x; acc.y += a * vv.y;
        acc.z += a * vv.z; acc.w += a * vv.w;
    }
    *(float4*)(out + (size_t)pix * C_ + lane * 4) = acc;
}

// ---------------------------------------------------------------------------
// Launch
// ---------------------------------------------------------------------------
extern "C" void kernel_launch(void* const* d_in, const int* in_sizes, int n_in,
                              void* d_out, int out_size)
{
    const float* x    = (const float*)d_in[0];
    const float* attn = (const float*)d_in[1];
    const int*   sp   = (const int*)  d_in[2];
    const float* Wv   = (const float*)d_in[3];
    const float* bv   = (const float*)d_in[4];
    const float* Wp   = (const float*)d_in[5];
    const float* bp   = (const float*)d_in[6];
    float*       out  = (float*)d_out;

    float* vbuf = nullptr;
    float* aggbuf = nullptr;
    __nv_bfloat16* wh = nullptr;
    __nv_bfloat16* wl = nullptr;
    cudaGetSymbolAddress((void**)&vbuf, g_v);
    cudaGetSymbolAddress((void**)&aggbuf, g_agg);
    cudaGetSymbolAddress((void**)&wh, g_wh);
    cudaGetSymbolAddress((void**)&wl, g_wl);

    cudaFuncSetAttribute(tc_gemm, cudaFuncAttributeMaxDynamicSharedMemorySize,
                         SM_TOTAL);

    prep_w<<<2, 256>>>(Wv, Wp);
    tc_gemm<<<NPIX / 128, 256, SM_TOTAL>>>(x, wh, wl, bv, vbuf);
    agg_kernel<<<NPIX / 8, 256>>>(vbuf, attn, sp, aggbuf);
    tc_gemm<<<NPIX / 128, 256, SM_TOTAL>>>(aggbuf, wh + C_ * C_,
                                           wl + C_ * C_, bp, out);
}